// round 14
// baseline (speedup 1.0000x reference)
#include <cuda_runtime.h>
#include <cstdint>

#define BATCH 8
#define SEQ   2048
#define EMBD  1024

#define TILE    128
#define STAGES  3
#define TILE_BYTES  16384           // 128 rows x 128B
#define STAGE_BYTES 32768           // A tile + B tile

// ---- scratch (__device__ globals; allocation is forbidden) ----
__device__ float g_Q [(size_t)BATCH*SEQ*EMBD];
__device__ float g_K [(size_t)BATCH*SEQ*EMBD];
__device__ float g_V [(size_t)BATCH*SEQ*EMBD];
__device__ float g_Vt[(size_t)BATCH*EMBD*SEQ];
__device__ float g_Xr[(size_t)BATCH*SEQ*EMBD];
__device__ float g_Cr[(size_t)BATCH*SEQ*EMBD];
__device__ float g_Wr[3*(size_t)EMBD*EMBD];     // Wq|Wk|Wv stacked
__device__ float g_rowsum[BATCH*SEQ];

__device__ __forceinline__ float f2tf32(float x){
  uint32_t u; asm("cvt.rna.tf32.f32 %0, %1;" : "=r"(u) : "f"(x));
  return __uint_as_float(u);
}
__device__ __forceinline__ void cp16s(uint32_t sm, const void* gm){
  asm volatile("cp.async.cg.shared.global [%0], [%1], 16;" :: "r"(sm), "l"(gm));
}
__device__ __forceinline__ void ldsm4(uint32_t& r0,uint32_t& r1,uint32_t& r2,uint32_t& r3,
                                      uint32_t s){
  asm volatile("ldmatrix.sync.aligned.m8n8.x4.shared.b16 {%0,%1,%2,%3}, [%4];"
    : "=r"(r0),"=r"(r1),"=r"(r2),"=r"(r3) : "r"(s));
}

// x and ctx tf32-rounded in one launch (z = 0:x 1:ctx)
__global__ void round_copy2(const float* __restrict__ a, const float* __restrict__ b,
                            float* __restrict__ da, float* __restrict__ db){
  const float* s = blockIdx.z ? b : a;
  float*       d = blockIdx.z ? db : da;
  const long i = (long)blockIdx.x*blockDim.x + threadIdx.x;
  float4 v = reinterpret_cast<const float4*>(s)[i];
  v.x = f2tf32(v.x); v.y = f2tf32(v.y); v.z = f2tf32(v.z); v.w = f2tf32(v.w);
  reinterpret_cast<float4*>(d)[i] = v;
}
// 3 weight matrices rounded + rowsum zeroed in one launch (z = 0..3)
__global__ void round_copy3z(const float* __restrict__ a, const float* __restrict__ b,
                             const float* __restrict__ c, float* __restrict__ dst,
                             float* __restrict__ rs){
  if (blockIdx.z == 3){
    const int i = blockIdx.x*blockDim.x + threadIdx.x;
    if (i < BATCH*SEQ) rs[i] = 0.f;
    return;
  }
  const float* s = blockIdx.z==0 ? a : (blockIdx.z==1 ? b : c);
  float* d = dst + (size_t)blockIdx.z*EMBD*EMBD;
  const long i = (long)blockIdx.x*blockDim.x + threadIdx.x;
  float4 v = reinterpret_cast<const float4*>(s)[i];
  v.x = f2tf32(v.x); v.y = f2tf32(v.y); v.z = f2tf32(v.z); v.w = f2tf32(v.w);
  reinterpret_cast<float4*>(d)[i] = v;
}

// ============================================================================
// tf32 GEMM:  C[m][n] = sum_k A[m][k] * B[n][k]   (nt, operands pre-rounded)
// MODE 0: fused QKV proj  (B rows 0..3071 = Wq|Wk|Wv; output/bias per CTA)
// MODE 1: scores          C = mask ? 0 : round(exp(scale*acc)); atomicAdd rowsum
// MODE 2: out             C = acc / rowsum[row]
// CTA 128x128x32, 256 thr, 8 warps (2x4), warp 64x32, SW128-XOR smem, 3-stage.
// ============================================================================
template<int MODE>
__global__ __launch_bounds__(256, 2)
void gemm_tf32(const float* __restrict__ Ag, const float* __restrict__ Aalt,
               const float* __restrict__ Bg,
               float* __restrict__ Cg, float* __restrict__ Cq1, float* __restrict__ Cq2,
               const float* __restrict__ bias, const float* __restrict__ bias1,
               const float* __restrict__ bias2,
               const int*   __restrict__ maskg, float* __restrict__ rowsum,
               int N, int Kd,
               long bA, long bB, long bC, long bM, int bRS,
               float scale)
{
  extern __shared__ float smem[];
  uint32_t smbase = (uint32_t)__cvta_generic_to_shared(smem);

  const int b  = blockIdx.z;
  const int m0 = blockIdx.y * TILE;
  const int n0 = blockIdx.x * TILE;

  const float* A;
  float*       C;
  const float* bs = bias;
  int n0l = n0;
  if constexpr (MODE == 0){
    const int mat = n0 >> 10;                // 0:Q 1:K 2:V
    n0l = n0 & 1023;
    A  = (mat == 0) ? Ag : Aalt;
    C  = (mat == 0) ? Cg : (mat == 1 ? Cq1 : Cq2);
    bs = (mat == 0) ? bias : (mat == 1 ? bias1 : bias2);
  } else {
    A = Ag + (long)b*bA;
    C = Cg + (long)b*bC;
  }
  const float* B = Bg + (long)b*bB;

  const int tid  = threadIdx.x;
  const int lane = tid & 31;
  const int warp = tid >> 5;
  const int wm = warp >> 2;   // 0..1
  const int wn = warp & 3;    // 0..3
  const int g  = lane >> 2;   // 0..7
  const int t  = lane & 3;    // 0..3

  // ldmatrix per-lane coordinates
  const int aR  = lane & 15;
  const int aC4 = (lane >> 4) & 1;
  const int bR  = (lane & 7) + ((lane & 16) >> 1);
  const int bC4 = (lane >> 3) & 1;

  float c[4][4][4];
  #pragma unroll
  for (int i=0;i<4;i++)
    #pragma unroll
    for (int j=0;j<4;j++){ c[i][j][0]=0.f;c[i][j][1]=0.f;c[i][j][2]=0.f;c[i][j][3]=0.f; }

  const int NT = Kd >> 5;

  auto fill = [&](int kt, int st){
    const int k0 = kt << 5;
    const uint32_t sa = smbase + st*STAGE_BYTES;
    const uint32_t sb = sa + TILE_BYTES;
    #pragma unroll
    for (int i=0;i<4;i++){
      const int idx = tid + (i<<8);        // 0..1023
      const int row = idx >> 3;
      const int ch  = idx & 7;
      const uint32_t off = (uint32_t)(row<<7) + (uint32_t)((ch ^ (row & 7)) << 4);
      cp16s(sa + off, A + (long)(m0+row)*Kd + k0 + (ch<<2));
      cp16s(sb + off, B + (long)(n0+row)*Kd + k0 + (ch<<2));
    }
    asm volatile("cp.async.commit_group;");
  };

  uint32_t af[4][4], bf[4][2];

  auto load_frags = [&](int st, int kk){
    const uint32_t sa = smbase + st*STAGE_BYTES;
    const uint32_t sb = sa + TILE_BYTES;
    const int kc = kk >> 2;
    #pragma unroll
    for (int mt=0; mt<4; mt++){
      const int R = wm*64 + mt*16 + aR;
      ldsm4(af[mt][0], af[mt][1], af[mt][2], af[mt][3],
            sa + (uint32_t)(R<<7) + (uint32_t)((((kc + aC4) ^ (R & 7))) << 4));
    }
    #pragma unroll
    for (int np=0; np<2; np++){
      const int R = wn*32 + np*16 + bR;
      ldsm4(bf[2*np][0], bf[2*np][1], bf[2*np+1][0], bf[2*np+1][1],
            sb + (uint32_t)(R<<7) + (uint32_t)((((kc + bC4) ^ (R & 7))) << 4));
    }
  };

  auto mmas = [&](){
    #pragma unroll
    for (int mt=0; mt<4; mt++)
      #pragma unroll
      for (int nt=0; nt<4; nt++){
        asm volatile(
          "mma.sync.aligned.m16n8k8.row.col.f32.tf32.tf32.f32 "
          "{%0,%1,%2,%3}, {%4,%5,%6,%7}, {%8,%9}, {%0,%1,%2,%3};"
          : "+f"(c[mt][nt][0]), "+f"(c[mt][nt][1]),
            "+f"(c[mt][nt][2]), "+f"(c[mt][nt][3])
          : "r"(af[mt][0]), "r"(af[mt][1]), "r"(af[mt][2]), "r"(af[mt][3]),
            "r"(bf[nt][0]), "r"(bf[nt][1]));
      }
  };

  fill(0, 0);
  if (NT > 1) fill(1, 1);

  for (int kt=0; kt<NT; kt++){
    const int cur = kt % STAGES;
    if (kt + STAGES - 1 < NT) fill(kt + STAGES - 1, (kt + STAGES - 1) % STAGES);
    else                      asm volatile("cp.async.commit_group;");
    asm volatile("cp.async.wait_group %0;" :: "n"(STAGES-1));
    __syncthreads();

    #pragma unroll
    for (int kk8=0; kk8<4; kk8++){
      load_frags(cur, kk8*8);
      mmas();
    }
    __syncthreads();
  }

  // ---------------- epilogues ----------------
  if constexpr (MODE == 0){
    #pragma unroll
    for (int mt=0; mt<4; mt++){
      const int r0 = m0 + wm*64 + mt*16 + g;
      #pragma unroll
      for (int nt=0; nt<4; nt++){
        const int cc = n0l + wn*32 + nt*8 + 2*t;
        const float b0 = bs[cc], b1 = bs[cc+1];
        *reinterpret_cast<float2*>(&C[(long)r0*N + cc]) =
            make_float2(f2tf32(c[mt][nt][0]+b0), f2tf32(c[mt][nt][1]+b1));
        *reinterpret_cast<float2*>(&C[(long)(r0+8)*N + cc]) =
            make_float2(f2tf32(c[mt][nt][2]+b0), f2tf32(c[mt][nt][3]+b1));
      }
    }
  } else if constexpr (MODE == 1){
    const int* Mk = maskg + (long)b*bM;
    #pragma unroll
    for (int mt=0; mt<4; mt++){
      float rs0 = 0.f, rs1 = 0.f;
      const int r0 = m0 + wm*64 + mt*16 + g;
      #pragma unroll
      for (int nt=0; nt<4; nt++){
        const int cc = n0 + wn*32 + nt*8 + 2*t;
        const long i0 = (long)r0*N + cc;
        const long i1 = (long)(r0+8)*N + cc;
        int2 m0v = *reinterpret_cast<const int2*>(&Mk[i0]);
        int2 m1v = *reinterpret_cast<const int2*>(&Mk[i1]);
        float e0 = m0v.x ? 0.f : f2tf32(__expf(c[mt][nt][0]*scale));
        float e1 = m0v.y ? 0.f : f2tf32(__expf(c[mt][nt][1]*scale));
        float e2 = m1v.x ? 0.f : f2tf32(__expf(c[mt][nt][2]*scale));
        float e3 = m1v.y ? 0.f : f2tf32(__expf(c[mt][nt][3]*scale));
        *reinterpret_cast<float2*>(&C[i0]) = make_float2(e0, e1);
        *reinterpret_cast<float2*>(&C[i1]) = make_float2(e2, e3);
        rs0 += e0 + e1;
        rs1 += e2 + e3;
      }
      rs0 += __shfl_xor_sync(0xffffffffu, rs0, 1);
      rs0 += __shfl_xor_sync(0xffffffffu, rs0, 2);
      rs1 += __shfl_xor_sync(0xffffffffu, rs1, 1);
      rs1 += __shfl_xor_sync(0xffffffffu, rs1, 2);
      if (t == 0){
        atomicAdd(&rowsum[b*bRS + r0    ], rs0);
        atomicAdd(&rowsum[b*bRS + r0 + 8], rs1);
      }
    }
  } else { // MODE 2
    #pragma unroll
    for (int mt=0; mt<4; mt++){
      const int r0 = m0 + wm*64 + mt*16 + g;
      const float inv0 = 1.0f / rowsum[b*bRS + r0    ];
      const float inv1 = 1.0f / rowsum[b*bRS + r0 + 8];
      #pragma unroll
      for (int nt=0; nt<4; nt++){
        const int cc = n0 + wn*32 + nt*8 + 2*t;
        *reinterpret_cast<float2*>(&C[(long)r0*N + cc])     = make_float2(c[mt][nt][0]*inv0, c[mt][nt][1]*inv0);
        *reinterpret_cast<float2*>(&C[(long)(r0+8)*N + cc]) = make_float2(c[mt][nt][2]*inv1, c[mt][nt][3]*inv1);
      }
    }
  }
}

// V [b][SEQ][EMBD] -> Vt [b][EMBD][SEQ]
__global__ void transpose_v(const float* __restrict__ src, float* __restrict__ dst){
  __shared__ float tile[32][33];
  const int b  = blockIdx.z;
  const int j0 = blockIdx.y * 32;
  const int k0 = blockIdx.x * 32;
  const float* s = src + (long)b*SEQ*EMBD;
  float*       d = dst + (long)b*EMBD*SEQ;
  const int x = threadIdx.x, y = threadIdx.y;
  #pragma unroll
  for (int r=0; r<32; r+=8)
    tile[y+r][x] = s[(long)(j0+y+r)*EMBD + k0 + x];
  __syncthreads();
  #pragma unroll
  for (int r=0; r<32; r+=8)
    d[(long)(k0+y+r)*SEQ + j0 + x] = tile[x][y+r];
}

// att (raw rounded exp) -> normalized, in place; 2 float4 per thread
__global__ __launch_bounds__(512)
void norm_att(float* __restrict__ att, const float* __restrict__ rowsum){
  const long base = ((long)blockIdx.x*512 + threadIdx.x)*2;
  const long row0 = base >> 9;          // 512 float4 per row
  const long row1 = (base+1) >> 9;
  const float inv0 = 1.0f / rowsum[row0];
  const float inv1 = 1.0f / rowsum[row1];
  float4 v0 = reinterpret_cast<float4*>(att)[base];
  float4 v1 = reinterpret_cast<float4*>(att)[base+1];
  v0.x *= inv0; v0.y *= inv0; v0.z *= inv0; v0.w *= inv0;
  v1.x *= inv1; v1.y *= inv1; v1.z *= inv1; v1.w *= inv1;
  reinterpret_cast<float4*>(att)[base]   = v0;
  reinterpret_cast<float4*>(att)[base+1] = v1;
}

extern "C" void kernel_launch(void* const* d_in, const int* in_sizes, int n_in,
                              void* d_out, int out_size)
{
  const float* x   = (const float*)d_in[0];
  const float* ctx = (const float*)d_in[1];
  const int*   msk = (const int*)  d_in[2];
  const float* Wq  = (const float*)d_in[3];
  const float* bq  = (const float*)d_in[4];
  const float* Wk  = (const float*)d_in[5];
  const float* bk  = (const float*)d_in[6];
  const float* Wv  = (const float*)d_in[7];
  const float* bv  = (const float*)d_in[8];

  float* out = (float*)d_out;                   // [8][2048][1024]
  float* att = out + (size_t)BATCH*SEQ*EMBD;    // [8][2048][2048]

  float *qp, *kp, *vp, *vtp, *rsp, *xr, *cr, *wr;
  cudaGetSymbolAddress((void**)&qp,  g_Q);
  cudaGetSymbolAddress((void**)&kp,  g_K);
  cudaGetSymbolAddress((void**)&vp,  g_V);
  cudaGetSymbolAddress((void**)&vtp, g_Vt);
  cudaGetSymbolAddress((void**)&rsp, g_rowsum);
  cudaGetSymbolAddress((void**)&xr,  g_Xr);
  cudaGetSymbolAddress((void**)&cr,  g_Cr);
  cudaGetSymbolAddress((void**)&wr,  g_Wr);

  const int SMEM = STAGES*STAGE_BYTES;   // 98304 B
  cudaFuncSetAttribute(gemm_tf32<0>, cudaFuncAttributeMaxDynamicSharedMemorySize, SMEM);
  cudaFuncSetAttribute(gemm_tf32<1>, cudaFuncAttributeMaxDynamicSharedMemorySize, SMEM);
  cudaFuncSetAttribute(gemm_tf32<2>, cudaFuncAttributeMaxDynamicSharedMemorySize, SMEM);

  const dim3 blk(256);

  // operand prep: x|ctx rounding, W rounding + rowsum zero
  round_copy2<<<dim3((int)((size_t)BATCH*SEQ*EMBD/4/256), 1, 2), 256>>>(x, ctx, xr, cr);
  round_copy3z<<<dim3(EMBD*EMBD/4/256, 1, 4), 256>>>(Wq, Wk, Wv, wr, rsp);

  // fused QKV projection  (M=16384, N=3072 concat, K=1024)
  gemm_tf32<0><<<dim3(3*EMBD/TILE, (BATCH*SEQ)/TILE, 1), blk, SMEM>>>(
      xr, cr, wr, qp, kp, vp, bq, bk, bv, nullptr, nullptr,
      EMBD, EMBD, 0,0,0,0,0, 1.f);

  // scores (M=SEQ, N=SEQ, K=EMBD)
  gemm_tf32<1><<<dim3(SEQ/TILE, SEQ/TILE, BATCH), blk, SMEM>>>(
      qp, nullptr, kp, att, nullptr, nullptr, nullptr, nullptr, nullptr,
      msk, rsp, SEQ, EMBD,
      (long)SEQ*EMBD, (long)SEQ*EMBD, (long)SEQ*SEQ, (long)SEQ*SEQ, SEQ, 0.03125f);

  // V transpose
  transpose_v<<<dim3(EMBD/32, SEQ/32, BATCH), dim3(32,8)>>>(vp, vtp);

  // out = (raw_exp . Vt^T)/rowsum   (M=SEQ, N=EMBD, K=SEQ)
  gemm_tf32<2><<<dim3(EMBD/TILE, SEQ/TILE, BATCH), blk, SMEM>>>(
      att, nullptr, vtp, out, nullptr, nullptr, nullptr, nullptr, nullptr,
      nullptr, rsp, EMBD, SEQ,
      (long)SEQ*SEQ, (long)EMBD*SEQ, (long)SEQ*EMBD, 0, SEQ, 1.f);

  // finalize att in place
  norm_att<<<(int)(((long)BATCH*SEQ*SEQ/8)/512), 512>>>(att, rsp);
}

// round 15
// speedup vs baseline: 1.5102x; 1.5102x over previous
#include <cuda_runtime.h>
#include <cstdint>

#define BATCH 8
#define SEQ   2048
#define EMBD  1024

#define TILE    128
#define STAGES  3
#define TILE_BYTES  16384           // 128 rows x 128B
#define STAGE_BYTES 32768           // A tile + B tile

// ---- scratch (__device__ globals; allocation is forbidden) ----
__device__ float g_Q [(size_t)BATCH*SEQ*EMBD];
__device__ float g_K [(size_t)BATCH*SEQ*EMBD];
__device__ float g_V [(size_t)BATCH*SEQ*EMBD];
__device__ float g_Vt[(size_t)BATCH*EMBD*SEQ];
__device__ float g_Xr[(size_t)BATCH*SEQ*EMBD];
__device__ float g_Cr[(size_t)BATCH*SEQ*EMBD];
__device__ float g_Wr[3*(size_t)EMBD*EMBD];     // Wq|Wk|Wv stacked: rows 0..3071
__device__ float g_rowsum[BATCH*SEQ];

__device__ __forceinline__ float f2tf32(float x){
  uint32_t u; asm("cvt.rna.tf32.f32 %0, %1;" : "=r"(u) : "f"(x));
  return __uint_as_float(u);
}
__device__ __forceinline__ void cp16s(uint32_t sm, const void* gm){
  asm volatile("cp.async.cg.shared.global [%0], [%1], 16;" :: "r"(sm), "l"(gm));
}
__device__ __forceinline__ void ldsm4(uint32_t& r0,uint32_t& r1,uint32_t& r2,uint32_t& r3,
                                      uint32_t s){
  asm volatile("ldmatrix.sync.aligned.m8n8.x4.shared.b16 {%0,%1,%2,%3}, [%4];"
    : "=r"(r0),"=r"(r1),"=r"(r2),"=r"(r3) : "r"(s));
}

// elementwise tf32 rounding
__global__ void round_copy(const float* __restrict__ src, float* __restrict__ dst){
  const long i = (long)blockIdx.x*blockDim.x + threadIdx.x;
  float4 v = reinterpret_cast<const float4*>(src)[i];
  v.x = f2tf32(v.x); v.y = f2tf32(v.y); v.z = f2tf32(v.z); v.w = f2tf32(v.w);
  reinterpret_cast<float4*>(dst)[i] = v;
}
// 3 weight matrices rounded + rowsum zeroed in one launch (z = 0..3)
__global__ void round_copy3z(const float* __restrict__ a, const float* __restrict__ b,
                             const float* __restrict__ c, float* __restrict__ dst,
                             float* __restrict__ rs){
  if (blockIdx.z == 3){
    const int i = blockIdx.x*blockDim.x + threadIdx.x;
    if (i < BATCH*SEQ) rs[i] = 0.f;
    return;
  }
  const float* s = blockIdx.z==0 ? a : (blockIdx.z==1 ? b : c);
  float* d = dst + (size_t)blockIdx.z*EMBD*EMBD;
  const long i = (long)blockIdx.x*blockDim.x + threadIdx.x;
  float4 v = reinterpret_cast<const float4*>(s)[i];
  v.x = f2tf32(v.x); v.y = f2tf32(v.y); v.z = f2tf32(v.z); v.w = f2tf32(v.w);
  reinterpret_cast<float4*>(d)[i] = v;
}

// ============================================================================
// tf32 GEMM:  C[m][n] = sum_k A[m][k] * B[n][k]   (nt, operands pre-rounded)
// MODE 0: fused QKV proj  (B rows 0..3071 = Wq|Wk|Wv; output/bias per CTA)
// MODE 1: scores          C = mask ? 0 : round(exp(scale*acc)); atomicAdd rowsum
// MODE 2: out             C = acc / rowsum[row]
// CTA 128x128x32, 256 thr, 8 warps (2x4), warp 64x32, SW128-XOR smem, 3-stage.
// ============================================================================
template<int MODE>
__global__ __launch_bounds__(256, 2)
void gemm_tf32(const float* __restrict__ Ag, const float* __restrict__ Aalt,
               const float* __restrict__ Bg,
               float* __restrict__ Cg, float* __restrict__ Cq1, float* __restrict__ Cq2,
               const float* __restrict__ bias, const float* __restrict__ bias1,
               const float* __restrict__ bias2,
               const int*   __restrict__ maskg, float* __restrict__ rowsum,
               int N, int Kd,
               long bA, long bB, long bC, long bM, int bRS,
               float scale)
{
  extern __shared__ float smem[];
  uint32_t smbase = (uint32_t)__cvta_generic_to_shared(smem);

  const int b  = blockIdx.z;
  const int m0 = blockIdx.y * TILE;
  const int n0 = blockIdx.x * TILE;

  const float* A;
  float*       C;
  const float* bs = bias;
  int n0l = n0;
  if constexpr (MODE == 0){
    const int mat = n0 >> 10;                // 0:Q 1:K 2:V
    n0l = n0 & 1023;
    A  = (mat == 0) ? Ag : Aalt;
    C  = (mat == 0) ? Cg : (mat == 1 ? Cq1 : Cq2);
    bs = (mat == 0) ? bias : (mat == 1 ? bias1 : bias2);
  } else {
    A = Ag + (long)b*bA;
    C = Cg + (long)b*bC;
  }
  const float* B = Bg + (long)b*bB;

  const int tid  = threadIdx.x;
  const int lane = tid & 31;
  const int warp = tid >> 5;
  const int wm = warp >> 2;   // 0..1
  const int wn = warp & 3;    // 0..3
  const int g  = lane >> 2;   // 0..7
  const int t  = lane & 3;    // 0..3

  // ldmatrix per-lane coordinates
  const int aR  = lane & 15;
  const int aC4 = (lane >> 4) & 1;
  const int bR  = (lane & 7) + ((lane & 16) >> 1);
  const int bC4 = (lane >> 3) & 1;

  float c[4][4][4];
  #pragma unroll
  for (int i=0;i<4;i++)
    #pragma unroll
    for (int j=0;j<4;j++){ c[i][j][0]=0.f;c[i][j][1]=0.f;c[i][j][2]=0.f;c[i][j][3]=0.f; }

  const int NT = Kd >> 5;

  auto fill = [&](int kt, int st){
    const int k0 = kt << 5;
    const uint32_t sa = smbase + st*STAGE_BYTES;
    const uint32_t sb = sa + TILE_BYTES;
    #pragma unroll
    for (int i=0;i<4;i++){
      const int idx = tid + (i<<8);        // 0..1023
      const int row = idx >> 3;
      const int ch  = idx & 7;
      const uint32_t off = (uint32_t)(row<<7) + (uint32_t)((ch ^ (row & 7)) << 4);
      cp16s(sa + off, A + (long)(m0+row)*Kd + k0 + (ch<<2));
      cp16s(sb + off, B + (long)(n0+row)*Kd + k0 + (ch<<2));
    }
    asm volatile("cp.async.commit_group;");
  };

  uint32_t af[4][4], bf[4][2];

  auto load_frags = [&](int st, int kk){
    const uint32_t sa = smbase + st*STAGE_BYTES;
    const uint32_t sb = sa + TILE_BYTES;
    const int kc = kk >> 2;
    #pragma unroll
    for (int mt=0; mt<4; mt++){
      const int R = wm*64 + mt*16 + aR;
      ldsm4(af[mt][0], af[mt][1], af[mt][2], af[mt][3],
            sa + (uint32_t)(R<<7) + (uint32_t)((((kc + aC4) ^ (R & 7))) << 4));
    }
    #pragma unroll
    for (int np=0; np<2; np++){
      const int R = wn*32 + np*16 + bR;
      ldsm4(bf[2*np][0], bf[2*np][1], bf[2*np+1][0], bf[2*np+1][1],
            sb + (uint32_t)(R<<7) + (uint32_t)((((kc + bC4) ^ (R & 7))) << 4));
    }
  };

  auto mmas = [&](){
    #pragma unroll
    for (int mt=0; mt<4; mt++)
      #pragma unroll
      for (int nt=0; nt<4; nt++){
        asm volatile(
          "mma.sync.aligned.m16n8k8.row.col.f32.tf32.tf32.f32 "
          "{%0,%1,%2,%3}, {%4,%5,%6,%7}, {%8,%9}, {%0,%1,%2,%3};"
          : "+f"(c[mt][nt][0]), "+f"(c[mt][nt][1]),
            "+f"(c[mt][nt][2]), "+f"(c[mt][nt][3])
          : "r"(af[mt][0]), "r"(af[mt][1]), "r"(af[mt][2]), "r"(af[mt][3]),
            "r"(bf[nt][0]), "r"(bf[nt][1]));
      }
  };

  fill(0, 0);
  if (NT > 1) fill(1, 1);

  for (int kt=0; kt<NT; kt++){
    const int cur = kt % STAGES;
    if (kt + STAGES - 1 < NT) fill(kt + STAGES - 1, (kt + STAGES - 1) % STAGES);
    else                      asm volatile("cp.async.commit_group;");
    asm volatile("cp.async.wait_group %0;" :: "n"(STAGES-1));
    __syncthreads();

    #pragma unroll
    for (int kk8=0; kk8<4; kk8++){
      load_frags(cur, kk8*8);
      mmas();
    }
    __syncthreads();
  }

  // ---------------- epilogues ----------------
  if constexpr (MODE == 0){
    #pragma unroll
    for (int mt=0; mt<4; mt++){
      const int r0 = m0 + wm*64 + mt*16 + g;
      #pragma unroll
      for (int nt=0; nt<4; nt++){
        const int cc = n0l + wn*32 + nt*8 + 2*t;
        const float b0 = bs[cc], b1 = bs[cc+1];
        *reinterpret_cast<float2*>(&C[(long)r0*N + cc]) =
            make_float2(f2tf32(c[mt][nt][0]+b0), f2tf32(c[mt][nt][1]+b1));
        *reinterpret_cast<float2*>(&C[(long)(r0+8)*N + cc]) =
            make_float2(f2tf32(c[mt][nt][2]+b0), f2tf32(c[mt][nt][3]+b1));
      }
    }
  } else if constexpr (MODE == 1){
    const int* Mk = maskg + (long)b*bM;
    #pragma unroll
    for (int mt=0; mt<4; mt++){
      float rs0 = 0.f, rs1 = 0.f;
      const int r0 = m0 + wm*64 + mt*16 + g;
      #pragma unroll
      for (int nt=0; nt<4; nt++){
        const int cc = n0 + wn*32 + nt*8 + 2*t;
        const long i0 = (long)r0*N + cc;
        const long i1 = (long)(r0+8)*N + cc;
        int2 m0v = *reinterpret_cast<const int2*>(&Mk[i0]);
        int2 m1v = *reinterpret_cast<const int2*>(&Mk[i1]);
        float e0 = m0v.x ? 0.f : f2tf32(__expf(c[mt][nt][0]*scale));
        float e1 = m0v.y ? 0.f : f2tf32(__expf(c[mt][nt][1]*scale));
        float e2 = m1v.x ? 0.f : f2tf32(__expf(c[mt][nt][2]*scale));
        float e3 = m1v.y ? 0.f : f2tf32(__expf(c[mt][nt][3]*scale));
        *reinterpret_cast<float2*>(&C[i0]) = make_float2(e0, e1);
        *reinterpret_cast<float2*>(&C[i1]) = make_float2(e2, e3);
        rs0 += e0 + e1;
        rs1 += e2 + e3;
      }
      rs0 += __shfl_xor_sync(0xffffffffu, rs0, 1);
      rs0 += __shfl_xor_sync(0xffffffffu, rs0, 2);
      rs1 += __shfl_xor_sync(0xffffffffu, rs1, 1);
      rs1 += __shfl_xor_sync(0xffffffffu, rs1, 2);
      if (t == 0){
        atomicAdd(&rowsum[b*bRS + r0    ], rs0);
        atomicAdd(&rowsum[b*bRS + r0 + 8], rs1);
      }
    }
  } else { // MODE 2
    #pragma unroll
    for (int mt=0; mt<4; mt++){
      const int r0 = m0 + wm*64 + mt*16 + g;
      const float inv0 = 1.0f / rowsum[b*bRS + r0    ];
      const float inv1 = 1.0f / rowsum[b*bRS + r0 + 8];
      #pragma unroll
      for (int nt=0; nt<4; nt++){
        const int cc = n0 + wn*32 + nt*8 + 2*t;
        *reinterpret_cast<float2*>(&C[(long)r0*N + cc])     = make_float2(c[mt][nt][0]*inv0, c[mt][nt][1]*inv0);
        *reinterpret_cast<float2*>(&C[(long)(r0+8)*N + cc]) = make_float2(c[mt][nt][2]*inv1, c[mt][nt][3]*inv1);
      }
    }
  }
}

// V [b][SEQ][EMBD] -> Vt [b][EMBD][SEQ]
__global__ void transpose_v(const float* __restrict__ src, float* __restrict__ dst){
  __shared__ float tile[32][33];
  const int b  = blockIdx.z;
  const int j0 = blockIdx.y * 32;
  const int k0 = blockIdx.x * 32;
  const float* s = src + (long)b*SEQ*EMBD;
  float*       d = dst + (long)b*EMBD*SEQ;
  const int x = threadIdx.x, y = threadIdx.y;
  #pragma unroll
  for (int r=0; r<32; r+=8)
    tile[y+r][x] = s[(long)(j0+y+r)*EMBD + k0 + x];
  __syncthreads();
  #pragma unroll
  for (int r=0; r<32; r+=8)
    d[(long)(k0+y+r)*SEQ + j0 + x] = tile[x][y+r];
}

// att (raw rounded exp) -> normalized, in place
__global__ void norm_att(float* __restrict__ att, const float* __restrict__ rowsum){
  const long gid = (long)blockIdx.x*blockDim.x + threadIdx.x;
  const long row = gid >> 9;
  const float inv = 1.0f / rowsum[row];
  float4 v = reinterpret_cast<float4*>(att)[gid];
  v.x *= inv; v.y *= inv; v.z *= inv; v.w *= inv;
  reinterpret_cast<float4*>(att)[gid] = v;
}

extern "C" void kernel_launch(void* const* d_in, const int* in_sizes, int n_in,
                              void* d_out, int out_size)
{
  const float* x   = (const float*)d_in[0];
  const float* ctx = (const float*)d_in[1];
  const int*   msk = (const int*)  d_in[2];
  const float* Wq  = (const float*)d_in[3];
  const float* bq  = (const float*)d_in[4];
  const float* Wk  = (const float*)d_in[5];
  const float* bk  = (const float*)d_in[6];
  const float* Wv  = (const float*)d_in[7];
  const float* bv  = (const float*)d_in[8];

  float* out = (float*)d_out;                   // [8][2048][1024]
  float* att = out + (size_t)BATCH*SEQ*EMBD;    // [8][2048][2048]

  float *qp, *kp, *vp, *vtp, *rsp, *xr, *cr, *wr;
  cudaGetSymbolAddress((void**)&qp,  g_Q);
  cudaGetSymbolAddress((void**)&kp,  g_K);
  cudaGetSymbolAddress((void**)&vp,  g_V);
  cudaGetSymbolAddress((void**)&vtp, g_Vt);
  cudaGetSymbolAddress((void**)&rsp, g_rowsum);
  cudaGetSymbolAddress((void**)&xr,  g_Xr);
  cudaGetSymbolAddress((void**)&cr,  g_Cr);
  cudaGetSymbolAddress((void**)&wr,  g_Wr);

  const int SMEM = STAGES*STAGE_BYTES;   // 98304 B
  cudaFuncSetAttribute(gemm_tf32<0>, cudaFuncAttributeMaxDynamicSharedMemorySize, SMEM);
  cudaFuncSetAttribute(gemm_tf32<1>, cudaFuncAttributeMaxDynamicSharedMemorySize, SMEM);
  cudaFuncSetAttribute(gemm_tf32<2>, cudaFuncAttributeMaxDynamicSharedMemorySize, SMEM);

  const dim3 blk(256);

  // operand prep
  round_copy<<<(int)((size_t)BATCH*SEQ*EMBD/4/256), 256>>>(x,   xr);
  round_copy<<<(int)((size_t)BATCH*SEQ*EMBD/4/256), 256>>>(ctx, cr);
  round_copy3z<<<dim3(EMBD*EMBD/4/256, 1, 4), 256>>>(Wq, Wk, Wv, wr, rsp);

  // fused QKV projection  (M=16384, N=3072 concat, K=1024)
  gemm_tf32<0><<<dim3(3*EMBD/TILE, (BATCH*SEQ)/TILE, 1), blk, SMEM>>>(
      xr, cr, wr, qp, kp, vp, bq, bk, bv, nullptr, nullptr,
      EMBD, EMBD, 0,0,0,0,0, 1.f);

  // scores (M=SEQ, N=SEQ, K=EMBD)
  gemm_tf32<1><<<dim3(SEQ/TILE, SEQ/TILE, BATCH), blk, SMEM>>>(
      qp, nullptr, kp, att, nullptr, nullptr, nullptr, nullptr, nullptr,
      msk, rsp, SEQ, EMBD,
      (long)SEQ*EMBD, (long)SEQ*EMBD, (long)SEQ*SEQ, (long)SEQ*SEQ, SEQ, 0.03125f);

  // V transpose
  transpose_v<<<dim3(EMBD/32, SEQ/32, BATCH), dim3(32,8)>>>(vp, vtp);

  // out = (raw_exp . Vt^T)/rowsum   (M=SEQ, N=EMBD, K=SEQ)
  gemm_tf32<2><<<dim3(EMBD/TILE, SEQ/TILE, BATCH), blk, SMEM>>>(
      att, nullptr, vtp, out, nullptr, nullptr, nullptr, nullptr, nullptr,
      nullptr, rsp, EMBD, SEQ,
      (long)SEQ*SEQ, (long)EMBD*SEQ, (long)SEQ*EMBD, 0, SEQ, 1.f);

  // finalize att in place
  norm_att<<<(int)(((long)BATCH*SEQ*SEQ/4)/256), 256>>>(att, rsp);
}

// round 17
// speedup vs baseline: 1.5284x; 1.0120x over previous
#include <cuda_runtime.h>
#include <cstdint>

#define BATCH 8
#define SEQ   2048
#define EMBD  1024

#define TILE    128
#define STAGES  3
#define TILE_BYTES  16384           // 128 rows x 128B
#define STAGE_BYTES 32768           // A tile + B tile

// ---- scratch (__device__ globals; allocation is forbidden) ----
__device__ float g_Q [(size_t)BATCH*SEQ*EMBD];
__device__ float g_K [(size_t)BATCH*SEQ*EMBD];
__device__ float g_V [(size_t)BATCH*SEQ*EMBD];
__device__ float g_Vt[(size_t)BATCH*EMBD*SEQ];
__device__ float g_Xr[(size_t)BATCH*SEQ*EMBD];
__device__ float g_Cr[(size_t)BATCH*SEQ*EMBD];
__device__ float g_Wr[3*(size_t)EMBD*EMBD];     // Wq|Wk|Wv stacked: rows 0..3071
__device__ float g_rowsum[BATCH*SEQ];

__device__ __forceinline__ float f2tf32(float x){
  uint32_t u; asm("cvt.rna.tf32.f32 %0, %1;" : "=r"(u) : "f"(x));
  return __uint_as_float(u);
}
__device__ __forceinline__ void cp16s(uint32_t sm, const void* gm){
  asm volatile("cp.async.cg.shared.global [%0], [%1], 16;" :: "r"(sm), "l"(gm));
}
__device__ __forceinline__ void ldsm4(uint32_t& r0,uint32_t& r1,uint32_t& r2,uint32_t& r3,
                                      uint32_t s){
  asm volatile("ldmatrix.sync.aligned.m8n8.x4.shared.b16 {%0,%1,%2,%3}, [%4];"
    : "=r"(r0),"=r"(r1),"=r"(r2),"=r"(r3) : "r"(s));
}

// elementwise tf32 rounding
__global__ void round_copy(const float* __restrict__ src, float* __restrict__ dst){
  const long i = (long)blockIdx.x*blockDim.x + threadIdx.x;
  float4 v = reinterpret_cast<const float4*>(src)[i];
  v.x = f2tf32(v.x); v.y = f2tf32(v.y); v.z = f2tf32(v.z); v.w = f2tf32(v.w);
  reinterpret_cast<float4*>(dst)[i] = v;
}
// 3 weight matrices rounded + rowsum zeroed in one launch (z = 0..3)
__global__ void round_copy3z(const float* __restrict__ a, const float* __restrict__ b,
                             const float* __restrict__ c, float* __restrict__ dst,
                             float* __restrict__ rs){
  if (blockIdx.z == 3){
    const int i = blockIdx.x*blockDim.x + threadIdx.x;
    if (i < BATCH*SEQ) rs[i] = 0.f;
    return;
  }
  const float* s = blockIdx.z==0 ? a : (blockIdx.z==1 ? b : c);
  float* d = dst + (size_t)blockIdx.z*EMBD*EMBD;
  const long i = (long)blockIdx.x*blockDim.x + threadIdx.x;
  float4 v = reinterpret_cast<const float4*>(s)[i];
  v.x = f2tf32(v.x); v.y = f2tf32(v.y); v.z = f2tf32(v.z); v.w = f2tf32(v.w);
  reinterpret_cast<float4*>(d)[i] = v;
}

// ============================================================================
// tf32 GEMM:  C[m][n] = sum_k A[m][k] * B[n][k]   (nt, operands pre-rounded)
// MODE 0: fused QKV proj  (B rows 0..3071 = Wq|Wk|Wv; output/bias per CTA)
// MODE 1: scores          C = mask ? 0 : round(exp(scale*acc)); atomicAdd rowsum
// MODE 2: out             C = acc / rowsum[row]
// CTA 128x128x32, 256 thr, 8 warps (2x4), warp 64x32, SW128-XOR smem,
// 3-stage cp.async, SINGLE barrier per K-tile (wait -> sync -> fill -> compute).
// ============================================================================
template<int MODE>
__global__ __launch_bounds__(256, 2)
void gemm_tf32(const float* __restrict__ Ag, const float* __restrict__ Aalt,
               const float* __restrict__ Bg,
               float* __restrict__ Cg, float* __restrict__ Cq1, float* __restrict__ Cq2,
               const float* __restrict__ bias, const float* __restrict__ bias1,
               const float* __restrict__ bias2,
               const int*   __restrict__ maskg, float* __restrict__ rowsum,
               int N, int Kd,
               long bA, long bB, long bC, long bM, int bRS,
               float scale)
{
  extern __shared__ float smem[];
  uint32_t smbase = (uint32_t)__cvta_generic_to_shared(smem);

  const int b  = blockIdx.z;
  const int m0 = blockIdx.y * TILE;
  const int n0 = blockIdx.x * TILE;

  const float* A;
  float*       C;
  const float* bs = bias;
  int n0l = n0;
  if constexpr (MODE == 0){
    const int mat = n0 >> 10;                // 0:Q 1:K 2:V
    n0l = n0 & 1023;
    A  = (mat == 0) ? Ag : Aalt;
    C  = (mat == 0) ? Cg : (mat == 1 ? Cq1 : Cq2);
    bs = (mat == 0) ? bias : (mat == 1 ? bias1 : bias2);
  } else {
    A = Ag + (long)b*bA;
    C = Cg + (long)b*bC;
  }
  const float* B = Bg + (long)b*bB;

  const int tid  = threadIdx.x;
  const int lane = tid & 31;
  const int warp = tid >> 5;
  const int wm = warp >> 2;   // 0..1
  const int wn = warp & 3;    // 0..3
  const int g  = lane >> 2;   // 0..7
  const int t  = lane & 3;    // 0..3

  // ldmatrix per-lane coordinates
  const int aR  = lane & 15;
  const int aC4 = (lane >> 4) & 1;
  const int bR  = (lane & 7) + ((lane & 16) >> 1);
  const int bC4 = (lane >> 3) & 1;

  float c[4][4][4];
  #pragma unroll
  for (int i=0;i<4;i++)
    #pragma unroll
    for (int j=0;j<4;j++){ c[i][j][0]=0.f;c[i][j][1]=0.f;c[i][j][2]=0.f;c[i][j][3]=0.f; }

  const int NT = Kd >> 5;

  auto fill = [&](int kt, int st){
    const int k0 = kt << 5;
    const uint32_t sa = smbase + st*STAGE_BYTES;
    const uint32_t sb = sa + TILE_BYTES;
    #pragma unroll
    for (int i=0;i<4;i++){
      const int idx = tid + (i<<8);        // 0..1023
      const int row = idx >> 3;
      const int ch  = idx & 7;
      const uint32_t off = (uint32_t)(row<<7) + (uint32_t)((ch ^ (row & 7)) << 4);
      cp16s(sa + off, A + (long)(m0+row)*Kd + k0 + (ch<<2));
      cp16s(sb + off, B + (long)(n0+row)*Kd + k0 + (ch<<2));
    }
    asm volatile("cp.async.commit_group;");
  };

  uint32_t af[4][4], bf[4][2];

  auto load_frags = [&](int st, int kk){
    const uint32_t sa = smbase + st*STAGE_BYTES;
    const uint32_t sb = sa + TILE_BYTES;
    const int kc = kk >> 2;
    #pragma unroll
    for (int mt=0; mt<4; mt++){
      const int R = wm*64 + mt*16 + aR;
      ldsm4(af[mt][0], af[mt][1], af[mt][2], af[mt][3],
            sa + (uint32_t)(R<<7) + (uint32_t)((((kc + aC4) ^ (R & 7))) << 4));
    }
    #pragma unroll
    for (int np=0; np<2; np++){
      const int R = wn*32 + np*16 + bR;
      ldsm4(bf[2*np][0], bf[2*np][1], bf[2*np+1][0], bf[2*np+1][1],
            sb + (uint32_t)(R<<7) + (uint32_t)((((kc + bC4) ^ (R & 7))) << 4));
    }
  };

  auto mmas = [&](){
    #pragma unroll
    for (int mt=0; mt<4; mt++)
      #pragma unroll
      for (int nt=0; nt<4; nt++){
        asm volatile(
          "mma.sync.aligned.m16n8k8.row.col.f32.tf32.tf32.f32 "
          "{%0,%1,%2,%3}, {%4,%5,%6,%7}, {%8,%9}, {%0,%1,%2,%3};"
          : "+f"(c[mt][nt][0]), "+f"(c[mt][nt][1]),
            "+f"(c[mt][nt][2]), "+f"(c[mt][nt][3])
          : "r"(af[mt][0]), "r"(af[mt][1]), "r"(af[mt][2]), "r"(af[mt][3]),
            "r"(bf[nt][0]), "r"(bf[nt][1]));
      }
  };

  // prologue: tiles 0 and 1 in flight
  fill(0, 0);
  if (NT > 1) fill(1, 1);

  // single-barrier multistage:
  //   wait(tile kt) -> barrier -> fill(tile kt+2, overwrites stage of kt-1) -> compute(kt)
  for (int kt=0; kt<NT; kt++){
    const int cur = kt % STAGES;
    asm volatile("cp.async.wait_group %0;" :: "n"(STAGES-2));
    __syncthreads();

    if (kt + STAGES - 1 < NT) fill(kt + STAGES - 1, (kt + STAGES - 1) % STAGES);
    else                      asm volatile("cp.async.commit_group;");

    #pragma unroll
    for (int kk8=0; kk8<4; kk8++){
      load_frags(cur, kk8*8);
      mmas();
    }
  }

  // ---------------- epilogues ----------------
  if constexpr (MODE == 0){
    #pragma unroll
    for (int mt=0; mt<4; mt++){
      const int r0 = m0 + wm*64 + mt*16 + g;
      #pragma unroll
      for (int nt=0; nt<4; nt++){
        const int cc = n0l + wn*32 + nt*8 + 2*t;
        const float b0 = bs[cc], b1 = bs[cc+1];
        *reinterpret_cast<float2*>(&C[(long)r0*N + cc]) =
            make_float2(f2tf32(c[mt][nt][0]+b0), f2tf32(c[mt][nt][1]+b1));
        *reinterpret_cast<float2*>(&C[(long)(r0+8)*N + cc]) =
            make_float2(f2tf32(c[mt][nt][2]+b0), f2tf32(c[mt][nt][3]+b1));
      }
    }
  } else if constexpr (MODE == 1){
    const int* Mk = maskg + (long)b*bM;
    #pragma unroll
    for (int mt=0; mt<4; mt++){
      float rs0 = 0.f, rs1 = 0.f;
      const int r0 = m0 + wm*64 + mt*16 + g;
      #pragma unroll
      for (int nt=0; nt<4; nt++){
        const int cc = n0 + wn*32 + nt*8 + 2*t;
        const long i0 = (long)r0*N + cc;
        const long i1 = (long)(r0+8)*N + cc;
        int2 m0v = *reinterpret_cast<const int2*>(&Mk[i0]);
        int2 m1v = *reinterpret_cast<const int2*>(&Mk[i1]);
        float e0 = m0v.x ? 0.f : f2tf32(__expf(c[mt][nt][0]*scale));
        float e1 = m0v.y ? 0.f : f2tf32(__expf(c[mt][nt][1]*scale));
        float e2 = m1v.x ? 0.f : f2tf32(__expf(c[mt][nt][2]*scale));
        float e3 = m1v.y ? 0.f : f2tf32(__expf(c[mt][nt][3]*scale));
        *reinterpret_cast<float2*>(&C[i0]) = make_float2(e0, e1);
        *reinterpret_cast<float2*>(&C[i1]) = make_float2(e2, e3);
        rs0 += e0 + e1;
        rs1 += e2 + e3;
      }
      rs0 += __shfl_xor_sync(0xffffffffu, rs0, 1);
      rs0 += __shfl_xor_sync(0xffffffffu, rs0, 2);
      rs1 += __shfl_xor_sync(0xffffffffu, rs1, 1);
      rs1 += __shfl_xor_sync(0xffffffffu, rs1, 2);
      if (t == 0){
        atomicAdd(&rowsum[b*bRS + r0    ], rs0);
        atomicAdd(&rowsum[b*bRS + r0 + 8], rs1);
      }
    }
  } else { // MODE 2
    #pragma unroll
    for (int mt=0; mt<4; mt++){
      const int r0 = m0 + wm*64 + mt*16 + g;
      const float inv0 = 1.0f / rowsum[b*bRS + r0    ];
      const float inv1 = 1.0f / rowsum[b*bRS + r0 + 8];
      #pragma unroll
      for (int nt=0; nt<4; nt++){
        const int cc = n0 + wn*32 + nt*8 + 2*t;
        *reinterpret_cast<float2*>(&C[(long)r0*N + cc])     = make_float2(c[mt][nt][0]*inv0, c[mt][nt][1]*inv0);
        *reinterpret_cast<float2*>(&C[(long)(r0+8)*N + cc]) = make_float2(c[mt][nt][2]*inv1, c[mt][nt][3]*inv1);
      }
    }
  }
}

// V [b][SEQ][EMBD] -> Vt [b][EMBD][SEQ]
__global__ void transpose_v(const float* __restrict__ src, float* __restrict__ dst){
  __shared__ float tile[32][33];
  const int b  = blockIdx.z;
  const int j0 = blockIdx.y * 32;
  const int k0 = blockIdx.x * 32;
  const float* s = src + (long)b*SEQ*EMBD;
  float*       d = dst + (long)b*EMBD*SEQ;
  const int x = threadIdx.x, y = threadIdx.y;
  #pragma unroll
  for (int r=0; r<32; r+=8)
    tile[y+r][x] = s[(long)(j0+y+r)*EMBD + k0 + x];
  __syncthreads();
  #pragma unroll
  for (int r=0; r<32; r+=8)
    d[(long)(k0+y+r)*SEQ + j0 + x] = tile[x][y+r];
}

// att (raw rounded exp) -> normalized, in place
__global__ void norm_att(float* __restrict__ att, const float* __restrict__ rowsum){
  const long gid = (long)blockIdx.x*blockDim.x + threadIdx.x;
  const long row = gid >> 9;
  const float inv = 1.0f / rowsum[row];
  float4 v = reinterpret_cast<float4*>(att)[gid];
  v.x *= inv; v.y *= inv; v.z *= inv; v.w *= inv;
  reinterpret_cast<float4*>(att)[gid] = v;
}

extern "C" void kernel_launch(void* const* d_in, const int* in_sizes, int n_in,
                              void* d_out, int out_size)
{
  const float* x   = (const float*)d_in[0];
  const float* ctx = (const float*)d_in[1];
  const int*   msk = (const int*)  d_in[2];
  const float* Wq  = (const float*)d_in[3];
  const float* bq  = (const float*)d_in[4];
  const float* Wk  = (const float*)d_in[5];
  const float* bk  = (const float*)d_in[6];
  const float* Wv  = (const float*)d_in[7];
  const float* bv  = (const float*)d_in[8];

  float* out = (float*)d_out;                   // [8][2048][1024]
  float* att = out + (size_t)BATCH*SEQ*EMBD;    // [8][2048][2048]

  float *qp, *kp, *vp, *vtp, *rsp, *xr, *cr, *wr;
  cudaGetSymbolAddress((void**)&qp,  g_Q);
  cudaGetSymbolAddress((void**)&kp,  g_K);
  cudaGetSymbolAddress((void**)&vp,  g_V);
  cudaGetSymbolAddress((void**)&vtp, g_Vt);
  cudaGetSymbolAddress((void**)&rsp, g_rowsum);
  cudaGetSymbolAddress((void**)&xr,  g_Xr);
  cudaGetSymbolAddress((void**)&cr,  g_Cr);
  cudaGetSymbolAddress((void**)&wr,  g_Wr);

  const int SMEM = STAGES*STAGE_BYTES;   // 98304 B
  cudaFuncSetAttribute(gemm_tf32<0>, cudaFuncAttributeMaxDynamicSharedMemorySize, SMEM);
  cudaFuncSetAttribute(gemm_tf32<1>, cudaFuncAttributeMaxDynamicSharedMemorySize, SMEM);
  cudaFuncSetAttribute(gemm_tf32<2>, cudaFuncAttributeMaxDynamicSharedMemorySize, SMEM);

  const dim3 blk(256);

  // operand prep
  round_copy<<<(int)((size_t)BATCH*SEQ*EMBD/4/256), 256>>>(x,   xr);
  round_copy<<<(int)((size_t)BATCH*SEQ*EMBD/4/256), 256>>>(ctx, cr);
  round_copy3z<<<dim3(EMBD*EMBD/4/256, 1, 4), 256>>>(Wq, Wk, Wv, wr, rsp);

  // fused QKV projection  (M=16384, N=3072 concat, K=1024)
  gemm_tf32<0><<<dim3(3*EMBD/TILE, (BATCH*SEQ)/TILE, 1), blk, SMEM>>>(
      xr, cr, wr, qp, kp, vp, bq, bk, bv, nullptr, nullptr,
      EMBD, EMBD, 0,0,0,0,0, 1.f);

  // scores (M=SEQ, N=SEQ, K=EMBD)
  gemm_tf32<1><<<dim3(SEQ/TILE, SEQ/TILE, BATCH), blk, SMEM>>>(
      qp, nullptr, kp, att, nullptr, nullptr, nullptr, nullptr, nullptr,
      msk, rsp, SEQ, EMBD,
      (long)SEQ*EMBD, (long)SEQ*EMBD, (long)SEQ*SEQ, (long)SEQ*SEQ, SEQ, 0.03125f);

  // V transpose
  transpose_v<<<dim3(EMBD/32, SEQ/32, BATCH), dim3(32,8)>>>(vp, vtp);

  // out = (raw_exp . Vt^T)/rowsum   (M=SEQ, N=EMBD, K=SEQ)
  gemm_tf32<2><<<dim3(EMBD/TILE, SEQ/TILE, BATCH), blk, SMEM>>>(
      att, nullptr, vtp, out, nullptr, nullptr, nullptr, nullptr, nullptr,
      nullptr, rsp, EMBD, SEQ,
      (long)SEQ*SEQ, (long)EMBD*SEQ, (long)SEQ*EMBD, 0, SEQ, 1.f);

  // finalize att in place
  norm_att<<<(int)(((long)BATCH*SEQ*SEQ/4)/256), 256>>>(att, rsp);
}